// round 5
// baseline (speedup 1.0000x reference)
#include <cuda_runtime.h>

typedef unsigned long long ull;
typedef unsigned int uint;

#define C_IN    64
#define INHW    224
#define XW      226            // padded dup-x width (cols 224,225 = edge copies)
#define C_OUT   128
#define OHW     222
#define OHW2    49284
#define ICC     8
#define NCHUNK  8
#define OC_TILE 64
#define TH      8
#define TW      16
#define XR      10             // input rows per chunk tile
#define XROWB   160            // smem bytes per dup row (18 dup used + pad)

#define WS_BYTES  (ICC*9*OC_TILE*4)      // 18432 plain-float weights
#define XS_BYTES  (ICC*XR*XROWB)         // 12800 dup-x tile
#define BUF_BYTES (WS_BYTES+XS_BYTES)    // 31232
#define SMEM_TOTAL (2*BUF_BYTES)         // 62464 -> occupancy 3

// x pre-duplicated to (v,v) pairs so cp.async stages FFMA2-ready operands verbatim.
__device__ __align__(16) float2 g_xdup[C_IN * INHW * XW];            // ~25.9 MB
// weights rearranged: [ocB(2)][c0b(8)][icr*9+k(72)][oc(64)] plain floats.
__device__ __align__(16) float g_wp[2 * NCHUNK * ICC * 9 * OC_TILE]; // 288 KB

__global__ void prep_xdup_kernel(const float* __restrict__ x) {
    int i = blockIdx.x * 256 + threadIdx.x;
    if (i >= C_IN * INHW * XW) return;
    int wc  = i % XW;
    int t   = i / XW;
    int h   = t % INHW;
    int c   = t / INHW;
    int sc  = wc > (INHW - 1) ? (INHW - 1) : wc;
    float v = x[(c * INHW + h) * INHW + sc];
    g_xdup[i] = make_float2(v, v);
}

__global__ void prep_w_kernel(const float* __restrict__ w) {
    int i = blockIdx.x * 256 + threadIdx.x;
    if (i >= C_OUT * C_IN * 9) return;
    int k  = i % 9;
    int t  = i / 9;
    int ic = t % C_IN;
    int oc = t / C_IN;
    int ocB = oc >> 6, ocr = oc & 63;
    int c0b = ic >> 3, icr = ic & 7;
    g_wp[((ocB * NCHUNK + c0b) * (ICC * 9) + icr * 9 + k) * OC_TILE + ocr] = w[i];
}

// ---- Blackwell packed f32x2 FMA (PTX-only -> FFMA2 in SASS) ----
__device__ __forceinline__ void fma2(ull& d, ull a, ull b) {
    asm("fma.rn.f32x2 %0, %1, %2, %0;" : "+l"(d) : "l"(a), "l"(b));
}
__device__ __forceinline__ float2 unpk(ull v) {
    float2 r; asm("mov.b64 {%0, %1}, %2;" : "=f"(r.x), "=f"(r.y) : "l"(v)); return r;
}

// ---- cp.async helpers ----
__device__ __forceinline__ void cpa16(uint d, const void* s) {
    asm volatile("cp.async.ca.shared.global [%0], [%1], 16;" :: "r"(d), "l"(s) : "memory");
}
__device__ __forceinline__ void cpa_commit() {
    asm volatile("cp.async.commit_group;" ::: "memory");
}
__device__ __forceinline__ void cpa_wait1() {
    asm volatile("cp.async.wait_group 1;" ::: "memory");
}
__device__ __forceinline__ void cpa_wait0() {
    asm volatile("cp.async.wait_group 0;" ::: "memory");
}

// Stage one chunk: weight slab (verbatim) + dup-x tile rows (row-clamped).
__device__ __forceinline__ void stage_chunk(
    int c0b, uint buf, int gx0, int gy0, int ocB, int tid)
{
    // weights: 18432B = 1152 x 16B, 9 per thread
    const char* slab = (const char*)&g_wp[(ocB * NCHUNK + c0b) * (ICC * 9) * OC_TILE];
    #pragma unroll
    for (int j = 0; j < 9; ++j) {
        int idx = tid + j * 128;
        cpa16(buf + idx * 16, slab + idx * 16);
    }
    // dup-x: ICC*XR rows x 9 chunks of 16B (18 dup values = 144B per row)
    uint xb = buf + WS_BYTES;
    #pragma unroll 1
    for (int idx = tid; idx < ICC * XR * 9; idx += 128) {
        int ic  = idx / (XR * 9);
        int rem = idx - ic * (XR * 9);
        int r   = rem / 9;
        int j   = rem - r * 9;
        int gr  = gy0 + r; gr = gr > (INHW - 1) ? (INHW - 1) : gr;
        const float2* src = g_xdup + ((size_t)((c0b * ICC + ic) * INHW) + gr) * XW
                                   + gx0 + j * 2;
        cpa16(xb + (ic * XR + r) * XROWB + j * 16, src);
    }
}

__global__ __launch_bounds__(128, 3)
void conv3x3_ocpair_kernel(float* __restrict__ out)
{
    extern __shared__ char smem[];

    const int tid  = threadIdx.x;
    const int ocg  = tid & 15;          // 16 groups of 4 oc
    const int colg = (tid >> 4) & 1;    // 8-pixel half
    const int rowg = tid >> 5;          // warp id = 2-output-row group (0..3)

    const int gx0 = blockIdx.x * TW;
    const int gy0 = blockIdx.y * TH;
    const int ocB = blockIdx.z;
    const int pxb = gx0 + colg * 8;

    // acc[r][p][j]: r=2 out rows, p=8 pixels, j=2 oc-pairs  (32 x f32x2)
    ull acc[32];
    #pragma unroll
    for (int i = 0; i < 32; ++i) acc[i] = 0ULL;

    uint sbase = (uint)__cvta_generic_to_shared(smem);

    stage_chunk(0, sbase, gx0, gy0, ocB, tid);
    cpa_commit();

    for (int c = 0; c < NCHUNK; ++c) {
        if (c + 1 < NCHUNK) {
            stage_chunk(c + 1, sbase + ((c + 1) & 1) * BUF_BYTES, gx0, gy0, ocB, tid);
            cpa_commit();
            cpa_wait1();
        } else {
            cpa_wait0();
        }
        __syncthreads();

        const char* buf = smem + (c & 1) * BUF_BYTES;
        const char* bw  = buf + (size_t)ocg * 16;
        const char* bx  = buf + WS_BYTES + (size_t)rowg * 2 * XROWB + colg * 64;

        #pragma unroll 1
        for (int ic = 0; ic < ICC; ++ic) {
            // hold all 9 weight taps: w[t] = 4 floats = 2 oc-pairs (aligned reg quads)
            uint4 wq[9];
            #pragma unroll
            for (int t = 0; t < 9; ++t)
                wq[t] = *(const uint4*)(bw + (ic * 9 + t) * (OC_TILE * 4));

            #pragma unroll
            for (int ri = 0; ri < 4; ++ri) {
                // load 10 dup pixels of input row (2*rowg + ri)
                const char* xr = bx + (ic * XR + ri) * XROWB;
                ull xv[10];
                {
                    ulonglong2 t0 = *(const ulonglong2*)(xr);
                    ulonglong2 t1 = *(const ulonglong2*)(xr + 16);
                    ulonglong2 t2 = *(const ulonglong2*)(xr + 32);
                    ulonglong2 t3 = *(const ulonglong2*)(xr + 48);
                    ulonglong2 t4 = *(const ulonglong2*)(xr + 64);
                    xv[0] = t0.x; xv[1] = t0.y; xv[2] = t1.x; xv[3] = t1.y;
                    xv[4] = t2.x; xv[5] = t2.y; xv[6] = t3.x; xv[7] = t3.y;
                    xv[8] = t4.x; xv[9] = t4.y;
                }
                // (out_r, kr) combos fed by this input row: kr = ri - out_r in [0,2]
                #pragma unroll
                for (int r = 0; r < 2; ++r) {
                    const int kr = ri - r;
                    if (kr >= 0 && kr <= 2) {
                        #pragma unroll
                        for (int ks = 0; ks < 3; ++ks) {
                            const ull* wp = (const ull*)&wq[kr * 3 + ks];
                            ull w0 = wp[0];   // (oc0, oc1)
                            ull w1 = wp[1];   // (oc2, oc3)
                            #pragma unroll
                            for (int p = 0; p < 8; ++p) {
                                fma2(acc[r * 16 + p * 2 + 0], w0, xv[ks + p]);
                                fma2(acc[r * 16 + p * 2 + 1], w1, xv[ks + p]);
                            }
                        }
                    }
                }
            }
        }
        __syncthreads();
    }

    // ---- epilogue: regroup per-oc rows and store float2 pairs ----
    const int np = ((OHW - pxb) < 16 ? (OHW - pxb) : 16) >> 1;  // full pixel-pairs (<=... 8 px -> <=4)
    const int npq = np < 4 ? np : 4;                            // pairs among this thread's 8 px
    #pragma unroll
    for (int r = 0; r < 2; ++r) {
        const int oh = gy0 + rowg * 2 + r;
        if (oh >= OHW) continue;
        #pragma unroll
        for (int j = 0; j < 2; ++j) {
            #pragma unroll
            for (int l = 0; l < 2; ++l) {
                const int oc = ocB * OC_TILE + ocg * 4 + j * 2 + l;
                float* orow = out + (size_t)oc * OHW2 + (size_t)oh * OHW + pxb;
                for (int q = 0; q < npq; ++q) {
                    float2 a = unpk(acc[r * 16 + (2 * q) * 2 + j]);
                    float2 b = unpk(acc[r * 16 + (2 * q + 1) * 2 + j]);
                    float2 v = make_float2(l ? a.y : a.x, l ? b.y : b.x);
                    *(float2*)(orow + 2 * q) = v;
                }
            }
        }
    }
}

extern "C" void kernel_launch(void* const* d_in, const int* in_sizes, int n_in,
                              void* d_out, int out_size)
{
    const float* x = (const float*)d_in[0];   // (64, 224, 224) f32
    const float* w = (const float*)d_in[1];   // (128, 64, 3, 3) f32
    float* out = (float*)d_out;               // (128, 222, 222) f32

    cudaFuncSetAttribute(conv3x3_ocpair_kernel,
                         cudaFuncAttributeMaxDynamicSharedMemorySize, SMEM_TOTAL);

    prep_xdup_kernel<<<(C_IN * INHW * XW + 255) / 256, 256>>>(x);
    prep_w_kernel<<<(C_OUT * C_IN * 9 + 255) / 256, 256>>>(w);

    dim3 grid((OHW + TW - 1) / TW,            // 14
              (OHW + TH - 1) / TH,            // 28
              C_OUT / OC_TILE);               // 2  -> 784 blocks
    conv3x3_ocpair_kernel<<<grid, 128, SMEM_TOTAL>>>(out);
}

// round 7
// speedup vs baseline: 2.2999x; 2.2999x over previous
#include <cuda_runtime.h>
#include <cuda_bf16.h>
#include <cstdint>

typedef unsigned int uint;

#define C_IN    64
#define INHW    224
#define C_OUT   128
#define OHW     222
#define NPIX    (OHW*OHW)          // 49284
#define NTAP    9
#define TILE_N  128
#define NTILES  ((NPIX + TILE_N - 1)/TILE_N)   // 386

// x transposed to [h][w][ic] bf16, split hi/lo (6.4 MB each)
__device__ __align__(16) __nv_bfloat16 g_xhi[INHW*INHW*C_IN];
__device__ __align__(16) __nv_bfloat16 g_xlo[INHW*INHW*C_IN];
// w rearranged to [tap][oc][ic] bf16, split hi/lo (144 KB each)
__device__ __align__(16) __nv_bfloat16 g_whi[NTAP*C_OUT*C_IN];
__device__ __align__(16) __nv_bfloat16 g_wlo[NTAP*C_OUT*C_IN];

// ---------------- prep kernels ----------------
__global__ void prep_x_kernel(const float* __restrict__ x) {
    int i = blockIdx.x * 256 + threadIdx.x;      // INHW*INHW*8 threads
    if (i >= INHW*INHW*8) return;
    int hw = i >> 3;
    int g  = i & 7;                               // ic group of 8
    __align__(16) __nv_bfloat16 hi[8];
    __align__(16) __nv_bfloat16 lo[8];
    #pragma unroll
    for (int q = 0; q < 8; ++q) {
        float v = x[(size_t)(g*8 + q) * (INHW*INHW) + hw];
        __nv_bfloat16 h = __float2bfloat16(v);
        hi[q] = h;
        lo[q] = __float2bfloat16(v - __bfloat162float(h));
    }
    *(uint4*)&g_xhi[(size_t)hw*64 + g*8] = *(const uint4*)hi;
    *(uint4*)&g_xlo[(size_t)hw*64 + g*8] = *(const uint4*)lo;
}

__global__ void prep_w_kernel(const float* __restrict__ w) {
    int i = blockIdx.x * 256 + threadIdx.x;      // 9*128*64 = 73728
    if (i >= NTAP*C_OUT*C_IN) return;
    int ic = i & 63;
    int r  = i >> 6;
    int oc = r & 127;
    int t  = r >> 7;
    float v = w[(size_t)(oc*C_IN + ic)*NTAP + t];
    __nv_bfloat16 h = __float2bfloat16(v);
    g_whi[i] = h;
    g_wlo[i] = __float2bfloat16(v - __bfloat162float(h));
}

// ---------------- PTX helpers (all sm_80-era, compute_103-safe) ----------------
__device__ __forceinline__ uint smem_u32(const void* p) {
    uint a;
    asm("{ .reg .u64 t; cvta.to.shared.u64 t, %1; cvt.u32.u64 %0, t; }"
        : "=r"(a) : "l"(p));
    return a;
}
__device__ __forceinline__ void cpa16(uint d, const void* s) {
    asm volatile("cp.async.ca.shared.global [%0], [%1], 16;" :: "r"(d), "l"(s) : "memory");
}
__device__ __forceinline__ void cpa_commit() {
    asm volatile("cp.async.commit_group;" ::: "memory");
}
__device__ __forceinline__ void cpa_wait0() {
    asm volatile("cp.async.wait_group 0;" ::: "memory");
}
__device__ __forceinline__ void ldsm4(uint& r0, uint& r1, uint& r2, uint& r3, uint a) {
    asm volatile("ldmatrix.sync.aligned.m8n8.x4.shared.b16 {%0,%1,%2,%3}, [%4];"
                 : "=r"(r0), "=r"(r1), "=r"(r2), "=r"(r3) : "r"(a));
}
__device__ __forceinline__ void mma_bf16(float* c, const uint* a, uint b0, uint b1) {
    asm volatile("mma.sync.aligned.m16n8k16.row.col.f32.bf16.bf16.f32 "
                 "{%0,%1,%2,%3}, {%4,%5,%6,%7}, {%8,%9}, {%0,%1,%2,%3};"
                 : "+f"(c[0]), "+f"(c[1]), "+f"(c[2]), "+f"(c[3])
                 : "r"(a[0]), "r"(a[1]), "r"(a[2]), "r"(a[3]), "r"(b0), "r"(b1));
}

// ---------------- SMEM layout (single buffer, 64 KB) ----------------
#define SM_A_HI   0
#define SM_A_LO   16384
#define SM_B_HI   32768
#define SM_B_LO   49152
#define SMEM_SZ   65536

// ---------------- main kernel ----------------
__global__ __launch_bounds__(256, 2)
void conv_hmma_kernel(float* __restrict__ out)
{
    extern __shared__ char smem[];
    const uint sb  = smem_u32(smem);
    const int tid  = threadIdx.x;
    const int wid  = tid >> 5;
    const int lid  = tid & 31;
    const int wm   = wid & 1;          // m-half (64 rows)
    const int wn   = wid >> 1;         // n-quarter (32 cols)

    const size_t p0 = (size_t)blockIdx.x * TILE_N;

    // ---- staging assignment (tid<128: A row 'tid'; tid>=128: B row 'tid-128') ----
    const int srow  = tid & 127;
    const int rowsw = srow & 7;                 // swizzle key for this staged row
    const char* srcH;                           // hi source base (w/o tap offset)
    const char* srcL;
    size_t tap_stride;                          // byte step per tap index (A) / per (kr,ks) (B uses table)
    int boh = 0, bow = 0;
    if (tid < 128) {
        srcH = (const char*)g_whi + (size_t)srow * 128;
        srcL = (const char*)g_wlo + (size_t)srow * 128;
        tap_stride = (size_t)C_OUT * 128;       // 16384 B per tap
    } else {
        size_t p = p0 + srow; if (p >= NPIX) p = NPIX - 1;   // masked at store
        boh = (int)(p / OHW); bow = (int)(p - (size_t)boh * OHW);
        srcH = (const char*)g_xhi + ((size_t)boh * INHW + bow) * 128;
        srcL = (const char*)g_xlo + ((size_t)boh * INHW + bow) * 128;
        tap_stride = 0;                         // B uses (kr*INHW+ks)*128 directly
    }
    const uint dA = sb + (tid < 128 ? SM_A_HI : SM_B_HI) + (uint)srow * 128;
    const uint dL = sb + (tid < 128 ? SM_A_LO : SM_B_LO) + (uint)srow * 128;

    // ---- ldmatrix per-lane bases ----
    // A: rows t0-15 -> m0-15, t16-31 -> same rows, next k-seg
    const int  rA = wm * 64 + (lid & 15);
    const int  sA = lid >> 4;
    const uint aHbase = sb + SM_A_HI + (uint)rA * 128;
    const uint aLbase = sb + SM_A_LO + (uint)rA * 128;
    // B: t0-7:n0-7 seg0, t8-15:n0-7 seg1, t16-23:n8-15 seg0, t24-31:n8-15 seg1
    const int  rB = wn * 32 + ((lid >> 4) << 3) + (lid & 7);
    const int  sB = (lid >> 3) & 1;
    const uint bHbase = sb + SM_B_HI + (uint)rB * 128;
    const uint bLbase = sb + SM_B_LO + (uint)rB * 128;
    const int  cA = rA & 7;                     // == lid&7
    const int  cB = rB & 7;                     // == lid&7

    float acc[64];
    #pragma unroll
    for (int i = 0; i < 64; ++i) acc[i] = 0.f;

    #pragma unroll 1
    for (int t = 0; t < NTAP; ++t) {
        __syncthreads();                         // previous tap's reads done before overwrite
        // ---- stage tap t (16 x cp.async.16 per thread) ----
        {
            const int kr = t / 3, ks = t - kr * 3;
            const size_t off = (tid < 128) ? (size_t)t * tap_stride
                                           : (size_t)(kr * INHW + ks) * 128;
            #pragma unroll
            for (int j = 0; j < 8; ++j) {
                const uint sw = (uint)((j ^ rowsw) << 4);
                cpa16(dA + sw, srcH + off + j * 16);
                cpa16(dL + sw, srcL + off + j * 16);
            }
        }
        cpa_commit();
        cpa_wait0();
        __syncthreads();

        // ---- compute: K=64 as 4 k16-steps, 3 passes fused ----
        #pragma unroll
        for (int k = 0; k < 4; ++k) {
            // B fragments: 4 n8-tiles -> regs [tile*2], [tile*2+1]
            uint bhi[8], blo[8];
            #pragma unroll
            for (int q = 0; q < 2; ++q) {
                const uint segoff = (uint)(((2 * k + sB) ^ cB) << 4) + (uint)q * 2048;
                ldsm4(bhi[q*4+0], bhi[q*4+1], bhi[q*4+2], bhi[q*4+3], bHbase + segoff);
                ldsm4(blo[q*4+0], blo[q*4+1], blo[q*4+2], blo[q*4+3], bLbase + segoff);
            }
            #pragma unroll
            for (int i = 0; i < 4; ++i) {
                const uint segA = (uint)(((2 * k + sA) ^ cA) << 4) + (uint)i * 2048;
                uint ahi[4], alo[4];
                ldsm4(ahi[0], ahi[1], ahi[2], ahi[3], aHbase + segA);
                ldsm4(alo[0], alo[1], alo[2], alo[3], aLbase + segA);
                #pragma unroll
                for (int j = 0; j < 4; ++j) {
                    float* c = &acc[(i * 4 + j) * 4];
                    mma_bf16(c, ahi, bhi[j*2], bhi[j*2+1]);   // Whi*Xhi
                    mma_bf16(c, ahi, blo[j*2], blo[j*2+1]);   // Whi*Xlo
                    mma_bf16(c, alo, bhi[j*2], bhi[j*2+1]);   // Wlo*Xhi
                }
            }
        }
    }

    // ---- epilogue: thread l of warp (wm,wn) holds C[m][n] per PTX frag layout ----
    // c0,c1 -> (m, n),(m, n+1); c2,c3 -> (m+8, n),(m+8, n+1)
    const int ml = wm * 64 + (lid >> 2);
    const int nl = wn * 32 + (lid & 3) * 2;
    #pragma unroll
    for (int i = 0; i < 4; ++i) {
        #pragma unroll
        for (int j = 0; j < 4; ++j) {
            const float* c = &acc[(i * 4 + j) * 4];
            const int n = nl + j * 8;
            const size_t p = p0 + n;
            if (p < NPIX) {                       // NPIX%4==0 -> pair fully valid
                const int m0 = ml + i * 16;
                *(float2*)(out + (size_t)m0 * NPIX + p)       = make_float2(c[0], c[1]);
                *(float2*)(out + (size_t)(m0 + 8) * NPIX + p) = make_float2(c[2], c[3]);
            }
        }
    }
}

// ---------------- launch ----------------
extern "C" void kernel_launch(void* const* d_in, const int* in_sizes, int n_in,
                              void* d_out, int out_size)
{
    const float* x = (const float*)d_in[0];   // (64, 224, 224) f32
    const float* w = (const float*)d_in[1];   // (128, 64, 3, 3) f32
    float* out = (float*)d_out;               // (128, 222, 222) f32

    cudaFuncSetAttribute(conv_hmma_kernel,
                         cudaFuncAttributeMaxDynamicSharedMemorySize, SMEM_SZ);

    prep_x_kernel<<<(INHW*INHW*8 + 255) / 256, 256>>>(x);
    prep_w_kernel<<<(NTAP*C_OUT*C_IN + 255) / 256, 256>>>(w);
    conv_hmma_kernel<<<NTILES, 256, SMEM_SZ>>>(out);
}